// round 1
// baseline (speedup 1.0000x reference)
#include <cuda_runtime.h>
#include <math.h>
#include <stdint.h>

// Problem constants
#define BB    2
#define TT    2048
#define CC    512
#define HH    8
#define DD    64
#define C3    1536          // 3*C
#define KSEL  4
#define GAMMA_F 2.5f
#define RHO_F   0.085f
#define TAUCLIP 5.0f

#define NROW  (BB*TT)       // 4096

// ---------------- scratch (device globals; no allocation allowed) ----------
__device__ float g_qkv[(size_t)NROW * C3];        // 6,291,456 floats (25 MB)
__device__ float g_attn_out[(size_t)NROW * CC];   // 2,097,152 floats
__device__ int   g_idx[NROW * KSEL];
__device__ float g_sig[NROW * KSEL];
__device__ float g_rowsum[NROW];
__device__ float g_invden[NROW];

// ---------------- top-K + rowsum per tau row ------------------------------
__global__ void topk_kernel(const float* __restrict__ tau) {
    const int row = blockIdx.x;                   // 0..NROW-1
    const float* tr = tau + (size_t)row * TT;
    __shared__ float sv[TT];                      // 8 KB
    __shared__ float red[256];
    __shared__ int   redi[256];
    const int tid = threadIdx.x;

    float sum = 0.f;
    #pragma unroll
    for (int i = tid; i < TT; i += 256) { float v = tr[i]; sv[i] = v; sum += v; }
    red[tid] = sum; __syncthreads();
    for (int s = 128; s > 0; s >>= 1) {
        if (tid < s) red[tid] += red[tid + s];
        __syncthreads();
    }
    if (tid == 0) g_rowsum[row] = red[0];
    __syncthreads();

    // 4 argmax passes; tie-break: smaller index wins (matches lax.top_k)
    for (int pass = 0; pass < KSEL; pass++) {
        float bv = -1e30f; int bi = TT;
        for (int i = tid; i < TT; i += 256) {
            float v = sv[i];
            if (v > bv || (v == bv && i < bi)) { bv = v; bi = i; }
        }
        red[tid] = bv; redi[tid] = bi; __syncthreads();
        for (int s = 128; s > 0; s >>= 1) {
            if (tid < s) {
                float ov = red[tid + s]; int oi = redi[tid + s];
                if (ov > red[tid] || (ov == red[tid] && oi < redi[tid])) {
                    red[tid] = ov; redi[tid] = oi;
                }
            }
            __syncthreads();
        }
        if (tid == 0) { g_idx[row * KSEL + pass] = redi[0]; sv[redi[0]] = -1e30f; }
        __syncthreads();
    }
}

// ---------------- fp32 SGEMM with bias: C[M,N] = A[M,K]*W[K,N] + bias -----
// BM=BN=128, BK=16, 256 threads, 8x8 register tile per thread.
// M,N,K all divisible by tile sizes for both calls (4096x1536x512, 4096x512x512).
__global__ __launch_bounds__(256) void sgemm_bias(
    const float* __restrict__ A, const float* __restrict__ W,
    const float* __restrict__ bias, float* __restrict__ Cout,
    int M, int N, int Kd)
{
    constexpr int BM = 128, BN = 128, BK = 16;
    __shared__ float As[BK][BM + 8];
    __shared__ float Bs[BK][BN + 8];

    const int tid = threadIdx.x;
    const int tx = tid & 15, ty = tid >> 4;       // 16x16 thread grid
    const int br = blockIdx.y * BM;
    const int bc = blockIdx.x * BN;

    float acc[8][8] = {};
    const float* Aptr = A + (size_t)br * Kd;
    const float* Wptr = W + bc;

    for (int k0 = 0; k0 < Kd; k0 += BK) {
        // load A tile 128x16 (512 float4s, 2 per thread), store transposed
        #pragma unroll
        for (int l = 0; l < 2; l++) {
            int f = tid + l * 256;
            int r = f >> 2, c4 = (f & 3) * 4;
            float4 v = *reinterpret_cast<const float4*>(Aptr + (size_t)r * Kd + k0 + c4);
            As[c4 + 0][r] = v.x; As[c4 + 1][r] = v.y;
            As[c4 + 2][r] = v.z; As[c4 + 3][r] = v.w;
        }
        // load W tile 16x128
        #pragma unroll
        for (int l = 0; l < 2; l++) {
            int f = tid + l * 256;
            int kr = f >> 5, c4 = (f & 31) * 4;
            float4 v = *reinterpret_cast<const float4*>(Wptr + (size_t)(k0 + kr) * N + c4);
            *reinterpret_cast<float4*>(&Bs[kr][c4]) = v;
        }
        __syncthreads();

        #pragma unroll
        for (int k = 0; k < BK; k++) {
            float a[8], b[8];
            float4 t0 = *reinterpret_cast<const float4*>(&As[k][ty * 8]);
            float4 t1 = *reinterpret_cast<const float4*>(&As[k][ty * 8 + 4]);
            a[0]=t0.x; a[1]=t0.y; a[2]=t0.z; a[3]=t0.w;
            a[4]=t1.x; a[5]=t1.y; a[6]=t1.z; a[7]=t1.w;
            float4 u0 = *reinterpret_cast<const float4*>(&Bs[k][tx * 8]);
            float4 u1 = *reinterpret_cast<const float4*>(&Bs[k][tx * 8 + 4]);
            b[0]=u0.x; b[1]=u0.y; b[2]=u0.z; b[3]=u0.w;
            b[4]=u1.x; b[5]=u1.y; b[6]=u1.z; b[7]=u1.w;
            #pragma unroll
            for (int i = 0; i < 8; i++)
                #pragma unroll
                for (int j = 0; j < 8; j++)
                    acc[i][j] = fmaf(a[i], b[j], acc[i][j]);
        }
        __syncthreads();
    }

    #pragma unroll
    for (int i = 0; i < 8; i++) {
        int r = br + ty * 8 + i;
        #pragma unroll
        for (int j = 0; j < 8; j += 4) {
            int c = bc + tx * 8 + j;
            float4 o;
            o.x = acc[i][j + 0] + bias[c + 0];
            o.y = acc[i][j + 1] + bias[c + 1];
            o.z = acc[i][j + 2] + bias[c + 2];
            o.w = acc[i][j + 3] + bias[c + 3];
            *reinterpret_cast<float4*>(Cout + (size_t)r * N + c) = o;
        }
    }
}

// ---------------- sparse attention: 1 block per (b,t), 1 warp per head ----
__global__ __launch_bounds__(256) void attn_kernel(const float* __restrict__ tau) {
    const int row = blockIdx.x;                   // b*T + t
    const int tid = threadIdx.x;
    const int warp = tid >> 5, lane = tid & 31;   // warp == head
    const int b = row / TT;

    __shared__ int   sidx[KSEL];
    __shared__ float sbias[KSEL];
    __shared__ float ssig[KSEL];

    if (tid < KSEL) {
        int id = g_idx[row * KSEL + tid];
        sidx[tid]  = id;
        sbias[tid] = GAMMA_F * logf(tau[(size_t)row * TT + id] + 1e-8f);
        ssig[tid]  = 0.f;
    }
    __syncthreads();

    const float* qp = g_qkv + (size_t)row * C3 + warp * DD;
    const float q0 = qp[lane], q1 = qp[lane + 32];

    float logit[KSEL];
    #pragma unroll
    for (int j = 0; j < KSEL; j++) {
        int s = sidx[j];
        const float* kp = g_qkv + (size_t)(b * TT + s) * C3 + CC + warp * DD;
        float p = q0 * kp[lane] + q1 * kp[lane + 32];
        #pragma unroll
        for (int o = 16; o > 0; o >>= 1) p += __shfl_xor_sync(0xffffffffu, p, o);
        logit[j] = p * 0.125f + sbias[j];          // scale = D^-0.5 = 0.125
    }
    float m = fmaxf(fmaxf(logit[0], logit[1]), fmaxf(logit[2], logit[3]));
    float e[KSEL], se = 0.f;
    #pragma unroll
    for (int j = 0; j < KSEL; j++) { e[j] = expf(logit[j] - m); se += e[j]; }
    float inv = 1.f / se;
    float w[KSEL];
    #pragma unroll
    for (int j = 0; j < KSEL; j++) w[j] = e[j] * inv;

    float o0 = 0.f, o1 = 0.f;
    #pragma unroll
    for (int j = 0; j < KSEL; j++) {
        const float* vp = g_qkv + (size_t)(b * TT + sidx[j]) * C3 + 2 * CC + warp * DD;
        o0 = fmaf(w[j], vp[lane], o0);
        o1 = fmaf(w[j], vp[lane + 32], o1);
    }
    float* op = g_attn_out + (size_t)row * CC + warp * DD;
    op[lane] = o0; op[lane + 32] = o1;

    if (lane == 0) {
        #pragma unroll
        for (int j = 0; j < KSEL; j++) atomicAdd(&ssig[j], w[j] * (1.0f / HH));
    }
    __syncthreads();
    if (tid == 0) {
        float rs = g_rowsum[row] * (1.0f - RHO_F);
        #pragma unroll
        for (int j = 0; j < KSEL; j++) {
            float s = ssig[j];
            g_sig[row * KSEL + j] = s;
            rs += s * s * s;
        }
        g_invden[row] = 1.f / (rs + 1e-8f);
    }
}

// ---------------- tau_new: streaming scale pass (float4) ------------------
__global__ void tau_scale(const float* __restrict__ tau, float* __restrict__ out) {
    size_t i = (size_t)blockIdx.x * 256 + threadIdx.x;     // float4 index
    const int row = (int)(i / (TT / 4));
    const float f = (1.0f - RHO_F) * g_invden[row];
    float4 v = reinterpret_cast<const float4*>(tau)[i];
    v.x = fminf(v.x * f, TAUCLIP);
    v.y = fminf(v.y * f, TAUCLIP);
    v.z = fminf(v.z * f, TAUCLIP);
    v.w = fminf(v.w * f, TAUCLIP);
    reinterpret_cast<float4*>(out)[i] = v;
}

// ---------------- tau_new: fixup at the 4 selected positions per row ------
__global__ void tau_fix(const float* __restrict__ tau, float* __restrict__ out) {
    int i = blockIdx.x * 256 + threadIdx.x;                // row*4 + j
    if (i >= NROW * KSEL) return;
    int row = i >> 2;
    int id = g_idx[i];
    float s = g_sig[i];
    float v = tau[(size_t)row * TT + id] * (1.0f - RHO_F) + s * s * s;
    out[(size_t)row * TT + id] = fminf(v * g_invden[row], TAUCLIP);
}

// ---------------- launch ---------------------------------------------------
extern "C" void kernel_launch(void* const* d_in, const int* in_sizes, int n_in,
                              void* d_out, int out_size) {
    const float* x     = (const float*)d_in[0];   // [B,T,C]
    const float* tau   = (const float*)d_in[1];   // [B,T,T]
    const float* Wqkv  = (const float*)d_in[2];   // [C,3C]
    const float* bqkv  = (const float*)d_in[3];   // [3C]
    const float* Wproj = (const float*)d_in[4];   // [C,C]
    const float* bproj = (const float*)d_in[5];   // [C]

    float* out_main = (float*)d_out;                         // [B,T,C]
    float* out_tau  = out_main + (size_t)NROW * CC;          // [B,T,T]

    void* p_qkv = nullptr; void* p_ao = nullptr;
    cudaGetSymbolAddress(&p_qkv, g_qkv);
    cudaGetSymbolAddress(&p_ao, g_attn_out);
    float* qkv = (float*)p_qkv;
    float* ao  = (float*)p_ao;

    // 1. top-4 + rowsum of tau per row
    topk_kernel<<<NROW, 256>>>(tau);

    // 2. QKV GEMM: [4096,512] x [512,1536]
    sgemm_bias<<<dim3(C3 / 128, NROW / 128), 256>>>(x, Wqkv, bqkv, qkv, NROW, C3, CC);

    // 3. sparse attention (4 keys/query) + signal + denominator
    attn_kernel<<<NROW, 256>>>(tau);

    // 4. tau_new streaming pass
    tau_scale<<<(NROW * TT / 4) / 256, 256>>>(tau, out_tau);

    // 5. tau_new fixup at the 16384 selected entries
    tau_fix<<<(NROW * KSEL + 255) / 256, 256>>>(tau, out_tau);

    // 6. proj GEMM: [4096,512] x [512,512] -> d_out
    sgemm_bias<<<dim3(CC / 128, NROW / 128), 256>>>(ao, Wproj, bproj, out_main, NROW, CC, CC);
}

// round 3
// speedup vs baseline: 1.6228x; 1.6228x over previous
#include <cuda_runtime.h>
#include <cuda_bf16.h>
#include <math.h>
#include <stdint.h>

// Problem constants
#define BB    2
#define TT    2048
#define CC    512
#define HH    8
#define DD    64
#define C3    1536          // 3*C
#define KSEL  4
#define GAMMA_F 2.5f
#define RHO_F   0.085f
#define TAUCLIP 5.0f
#define NROW  (BB*TT)       // 4096
#define KTOT  512           // GEMM K for both GEMMs

// ---------------- scratch (device globals; no allocation allowed) ----------
__device__ float g_qkv[(size_t)NROW * C3];        // 24 MB
__device__ float g_attn_out[(size_t)NROW * CC];   // 8 MB
__device__ int   g_idx[NROW * KSEL];
__device__ float g_sig[NROW * KSEL];
__device__ float g_rowsum[NROW];
__device__ float g_invden[NROW];
// bf16 split operands
__device__ __nv_bfloat16 g_a_hi[(size_t)NROW * KTOT];
__device__ __nv_bfloat16 g_a_lo[(size_t)NROW * KTOT];
__device__ __nv_bfloat16 g_wt_hi[(size_t)C3 * KTOT];   // Wqkv^T [1536,512]
__device__ __nv_bfloat16 g_wt_lo[(size_t)C3 * KTOT];
__device__ __nv_bfloat16 g_wp_hi[(size_t)CC * KTOT];   // Wproj^T [512,512]
__device__ __nv_bfloat16 g_wp_lo[(size_t)CC * KTOT];
__device__ __nv_bfloat16 g_ao_hi[(size_t)NROW * KTOT];
__device__ __nv_bfloat16 g_ao_lo[(size_t)NROW * KTOT];

// ===================== small helpers ========================================
__device__ __forceinline__ uint32_t smem_u32(const void* p) {
    uint32_t a;
    asm("{ .reg .u64 t; cvta.to.shared.u64 t, %1; cvt.u32.u64 %0, t; }" : "=r"(a) : "l"(p));
    return a;
}
__device__ __forceinline__ void ldsm_x4(uint32_t& r0, uint32_t& r1, uint32_t& r2, uint32_t& r3,
                                        uint32_t addr) {
    asm volatile("ldmatrix.sync.aligned.m8n8.x4.shared.b16 {%0,%1,%2,%3}, [%4];"
                 : "=r"(r0), "=r"(r1), "=r"(r2), "=r"(r3) : "r"(addr));
}
__device__ __forceinline__ void mma16816(float* d, const uint32_t* a, uint32_t b0, uint32_t b1) {
    asm volatile("mma.sync.aligned.m16n8k16.row.col.f32.bf16.bf16.f32 "
                 "{%0,%1,%2,%3}, {%4,%5,%6,%7}, {%8,%9}, {%0,%1,%2,%3};"
                 : "+f"(d[0]), "+f"(d[1]), "+f"(d[2]), "+f"(d[3])
                 : "r"(a[0]), "r"(a[1]), "r"(a[2]), "r"(a[3]), "r"(b0), "r"(b1));
}

// ===================== top-K + rowsum per tau row ===========================
__global__ void topk_kernel(const float* __restrict__ tau) {
    const int row = blockIdx.x;
    const float* tr = tau + (size_t)row * TT;
    __shared__ float sv[TT];
    __shared__ float red[256];
    __shared__ int   redi[256];
    const int tid = threadIdx.x;

    float sum = 0.f;
    #pragma unroll
    for (int i = tid; i < TT; i += 256) { float v = tr[i]; sv[i] = v; sum += v; }
    red[tid] = sum; __syncthreads();
    for (int s = 128; s > 0; s >>= 1) {
        if (tid < s) red[tid] += red[tid + s];
        __syncthreads();
    }
    if (tid == 0) g_rowsum[row] = red[0];
    __syncthreads();

    for (int pass = 0; pass < KSEL; pass++) {
        float bv = -1e30f; int bi = TT;
        for (int i = tid; i < TT; i += 256) {
            float v = sv[i];
            if (v > bv || (v == bv && i < bi)) { bv = v; bi = i; }
        }
        red[tid] = bv; redi[tid] = bi; __syncthreads();
        for (int s = 128; s > 0; s >>= 1) {
            if (tid < s) {
                float ov = red[tid + s]; int oi = redi[tid + s];
                if (ov > red[tid] || (ov == red[tid] && oi < redi[tid])) {
                    red[tid] = ov; redi[tid] = oi;
                }
            }
            __syncthreads();
        }
        if (tid == 0) { g_idx[row * KSEL + pass] = redi[0]; sv[redi[0]] = -1e30f; }
        __syncthreads();
    }
}

// ===================== bf16 hi/lo split (elementwise) =======================
__global__ void convert_split(const float* __restrict__ in,
                              __nv_bfloat16* __restrict__ hi,
                              __nv_bfloat16* __restrict__ lo, int n) {
    int i = blockIdx.x * 256 + threadIdx.x;
    if (i < n) {
        float v = in[i];
        __nv_bfloat16 h = __float2bfloat16(v);
        hi[i] = h;
        lo[i] = __float2bfloat16(v - __bfloat162float(h));
    }
}

// ===================== transpose + bf16 hi/lo split =========================
// W: [K, N] fp32 -> out hi/lo: [N, K] bf16
__global__ void transpose_split(const float* __restrict__ W,
                                __nv_bfloat16* __restrict__ hi,
                                __nv_bfloat16* __restrict__ lo, int K, int N) {
    __shared__ float tile[32][33];
    int n0 = blockIdx.x * 32, k0 = blockIdx.y * 32;
    int tx = threadIdx.x, ty = threadIdx.y;   // block(32,8)
    #pragma unroll
    for (int i = 0; i < 32; i += 8)
        tile[ty + i][tx] = W[(size_t)(k0 + ty + i) * N + n0 + tx];
    __syncthreads();
    #pragma unroll
    for (int i = 0; i < 32; i += 8) {
        float v = tile[tx][ty + i];
        __nv_bfloat16 h = __float2bfloat16(v);
        size_t o = (size_t)(n0 + ty + i) * K + k0 + tx;
        hi[o] = h;
        lo[o] = __float2bfloat16(v - __bfloat162float(h));
    }
}

// ===================== 3x-bf16 HMMA GEMM ====================================
// C[M,N] = A[M,512] * B^T + bias ; A,B given as hi/lo bf16 [rows,512] K-major.
// Block: 128x128, BK=32, 3-stage cp.async, 8 warps (4 x m, 2 x n), warp 32x64.
#define GBK 32
#define NCHUNK (KTOT / GBK)          // 16
#define ROWPAD 40                    // elems per smem row (80 B)
#define TILE_B (128 * ROWPAD * 2)    // 10240 B per tile
#define STAGE_B (4 * TILE_B)         // Ahi,Alo,Bhi,Blo = 40960 B
#define NSTAGE 3
#define GEMM_SMEM (NSTAGE * STAGE_B) // 122880 B

__device__ __forceinline__ void gemm_load_chunk(
    uint32_t sm_base, int stage, int c, int m0, int n0, int tid,
    const __nv_bfloat16* __restrict__ Ahi, const __nv_bfloat16* __restrict__ Alo,
    const __nv_bfloat16* __restrict__ Bhi, const __nv_bfloat16* __restrict__ Blo)
{
    if (c < NCHUNK) {
        uint32_t sbase = sm_base + stage * STAGE_B;
        const int k0 = c * GBK;
        const __nv_bfloat16* srcs[4] = {Ahi, Alo, Bhi, Blo};
        #pragma unroll
        for (int t = 0; t < 4; t++) {
            const int rowbase = (t < 2) ? m0 : n0;
            #pragma unroll
            for (int i = 0; i < 2; i++) {
                int u = tid + i * 256;            // 0..511 (128 rows x 4 x16B)
                int row = u >> 2, c16 = u & 3;
                const void* gp = srcs[t] + (size_t)(rowbase + row) * KTOT + k0 + c16 * 8;
                uint32_t dst = sbase + t * TILE_B + row * (ROWPAD * 2) + c16 * 16;
                asm volatile("cp.async.cg.shared.global [%0], [%1], 16;" :: "r"(dst), "l"(gp));
            }
        }
    }
    asm volatile("cp.async.commit_group;" ::: "memory");
}

__global__ __launch_bounds__(256) void gemm3_kernel(
    const __nv_bfloat16* __restrict__ Ahi, const __nv_bfloat16* __restrict__ Alo,
    const __nv_bfloat16* __restrict__ Bhi, const __nv_bfloat16* __restrict__ Blo,
    const float* __restrict__ bias, float* __restrict__ Cout, int N)
{
    extern __shared__ char smem[];
    const uint32_t sm_base = smem_u32(smem);
    const int tid = threadIdx.x;
    const int wid = tid >> 5, lane = tid & 31;
    const int wm = wid >> 1, wn = wid & 1;       // warp grid 4x2
    const int m0 = blockIdx.y * 128;
    const int n0 = blockIdx.x * 128;

    float acc[2][8][4];
    #pragma unroll
    for (int i = 0; i < 2; i++)
        #pragma unroll
        for (int j = 0; j < 8; j++)
            #pragma unroll
            for (int l = 0; l < 4; l++) acc[i][j][l] = 0.f;

    gemm_load_chunk(sm_base, 0, 0, m0, n0, tid, Ahi, Alo, Bhi, Blo);
    gemm_load_chunk(sm_base, 1, 1, m0, n0, tid, Ahi, Alo, Bhi, Blo);

    // ldmatrix address pieces (within a tile): row*(80) + col*2
    const int lrow = lane & 15;                  // row within 16-row group
    const int lcol = (lane >> 4) << 3;           // 0 or 8 (k offset)

    for (int c = 0; c < NCHUNK; c++) {
        asm volatile("cp.async.wait_group 1;" ::: "memory");
        __syncthreads();
        gemm_load_chunk(sm_base, (c + 2) % NSTAGE, c + 2, m0, n0, tid, Ahi, Alo, Bhi, Blo);

        const uint32_t stg = sm_base + (c % NSTAGE) * STAGE_B;
        #pragma unroll
        for (int kk = 0; kk < 2; kk++) {         // two k16 steps per chunk
            const int kc = kk * 16 + lcol;
            uint32_t ah[2][4], al[2][4], bh[4][4], bl[4][4];
            #pragma unroll
            for (int im = 0; im < 2; im++) {
                uint32_t ra = (wm * 32 + im * 16 + lrow) * (ROWPAD * 2) + kc * 2;
                ldsm_x4(ah[im][0], ah[im][1], ah[im][2], ah[im][3], stg + 0 * TILE_B + ra);
                ldsm_x4(al[im][0], al[im][1], al[im][2], al[im][3], stg + 1 * TILE_B + ra);
            }
            #pragma unroll
            for (int jn = 0; jn < 4; jn++) {     // 4 n16-groups = 64 cols
                uint32_t rb = (wn * 64 + jn * 16 + lrow) * (ROWPAD * 2) + kc * 2;
                ldsm_x4(bh[jn][0], bh[jn][1], bh[jn][2], bh[jn][3], stg + 2 * TILE_B + rb);
                ldsm_x4(bl[jn][0], bl[jn][1], bl[jn][2], bl[jn][3], stg + 3 * TILE_B + rb);
            }
            #pragma unroll
            for (int im = 0; im < 2; im++) {
                #pragma unroll
                for (int jn = 0; jn < 4; jn++) {
                    // n-frag jn*2   : regs {0,2};  n-frag jn*2+1 : regs {1,3}
                    mma16816(acc[im][jn * 2],     ah[im], bh[jn][0], bh[jn][2]);
                    mma16816(acc[im][jn * 2],     ah[im], bl[jn][0], bl[jn][2]);
                    mma16816(acc[im][jn * 2],     al[im], bh[jn][0], bh[jn][2]);
                    mma16816(acc[im][jn * 2 + 1], ah[im], bh[jn][1], bh[jn][3]);
                    mma16816(acc[im][jn * 2 + 1], ah[im], bl[jn][1], bl[jn][3]);
                    mma16816(acc[im][jn * 2 + 1], al[im], bh[jn][1], bh[jn][3]);
                }
            }
        }
    }

    // epilogue: fragment layout m16n8: c0,c1 -> row (lane>>2), cols (lane&3)*2;
    // c2,c3 -> row +8.
    #pragma unroll
    for (int im = 0; im < 2; im++) {
        int rbase = m0 + wm * 32 + im * 16 + (lane >> 2);
        #pragma unroll
        for (int jf = 0; jf < 8; jf++) {
            int col = n0 + wn * 64 + jf * 8 + (lane & 3) * 2;
            float2 b2 = *reinterpret_cast<const float2*>(bias + col);
            float2 o0, o1;
            o0.x = acc[im][jf][0] + b2.x; o0.y = acc[im][jf][1] + b2.y;
            o1.x = acc[im][jf][2] + b2.x; o1.y = acc[im][jf][3] + b2.y;
            *reinterpret_cast<float2*>(Cout + (size_t)rbase * N + col) = o0;
            *reinterpret_cast<float2*>(Cout + (size_t)(rbase + 8) * N + col) = o1;
        }
    }
}

// ===================== sparse attention =====================================
__global__ __launch_bounds__(256) void attn_kernel(const float* __restrict__ tau) {
    const int row = blockIdx.x;
    const int tid = threadIdx.x;
    const int warp = tid >> 5, lane = tid & 31;   // warp == head
    const int b = row / TT;

    __shared__ int   sidx[KSEL];
    __shared__ float sbias[KSEL];
    __shared__ float ssig[KSEL];

    if (tid < KSEL) {
        int id = g_idx[row * KSEL + tid];
        sidx[tid]  = id;
        sbias[tid] = GAMMA_F * logf(tau[(size_t)row * TT + id] + 1e-8f);
        ssig[tid]  = 0.f;
    }
    __syncthreads();

    const float* qp = g_qkv + (size_t)row * C3 + warp * DD;
    const float q0 = qp[lane], q1 = qp[lane + 32];

    float logit[KSEL];
    #pragma unroll
    for (int j = 0; j < KSEL; j++) {
        int s = sidx[j];
        const float* kp = g_qkv + (size_t)(b * TT + s) * C3 + CC + warp * DD;
        float p = q0 * kp[lane] + q1 * kp[lane + 32];
        #pragma unroll
        for (int o = 16; o > 0; o >>= 1) p += __shfl_xor_sync(0xffffffffu, p, o);
        logit[j] = p * 0.125f + sbias[j];
    }
    float m = fmaxf(fmaxf(logit[0], logit[1]), fmaxf(logit[2], logit[3]));
    float e[KSEL], se = 0.f;
    #pragma unroll
    for (int j = 0; j < KSEL; j++) { e[j] = expf(logit[j] - m); se += e[j]; }
    float inv = 1.f / se;
    float w[KSEL];
    #pragma unroll
    for (int j = 0; j < KSEL; j++) w[j] = e[j] * inv;

    float o0 = 0.f, o1 = 0.f;
    #pragma unroll
    for (int j = 0; j < KSEL; j++) {
        const float* vp = g_qkv + (size_t)(b * TT + sidx[j]) * C3 + 2 * CC + warp * DD;
        o0 = fmaf(w[j], vp[lane], o0);
        o1 = fmaf(w[j], vp[lane + 32], o1);
    }
    float* op = g_attn_out + (size_t)row * CC + warp * DD;
    op[lane] = o0; op[lane + 32] = o1;

    if (lane == 0) {
        #pragma unroll
        for (int j = 0; j < KSEL; j++) atomicAdd(&ssig[j], w[j] * (1.0f / HH));
    }
    __syncthreads();
    if (tid == 0) {
        float rs = g_rowsum[row] * (1.0f - RHO_F);
        #pragma unroll
        for (int j = 0; j < KSEL; j++) {
            float s = ssig[j];
            g_sig[row * KSEL + j] = s;
            rs += s * s * s;
        }
        g_invden[row] = 1.f / (rs + 1e-8f);
    }
}

// ===================== tau_new passes =======================================
__global__ void tau_scale(const float* __restrict__ tau, float* __restrict__ out) {
    size_t i = (size_t)blockIdx.x * 256 + threadIdx.x;
    const int row = (int)(i / (TT / 4));
    const float f = (1.0f - RHO_F) * g_invden[row];
    float4 v = reinterpret_cast<const float4*>(tau)[i];
    v.x = fminf(v.x * f, TAUCLIP);
    v.y = fminf(v.y * f, TAUCLIP);
    v.z = fminf(v.z * f, TAUCLIP);
    v.w = fminf(v.w * f, TAUCLIP);
    reinterpret_cast<float4*>(out)[i] = v;
}

__global__ void tau_fix(const float* __restrict__ tau, float* __restrict__ out) {
    int i = blockIdx.x * 256 + threadIdx.x;
    if (i >= NROW * KSEL) return;
    int row = i >> 2;
    int id = g_idx[i];
    float s = g_sig[i];
    float v = tau[(size_t)row * TT + id] * (1.0f - RHO_F) + s * s * s;
    out[(size_t)row * TT + id] = fminf(v * g_invden[row], TAUCLIP);
}

// ===================== launch ===============================================
extern "C" void kernel_launch(void* const* d_in, const int* in_sizes, int n_in,
                              void* d_out, int out_size) {
    const float* x     = (const float*)d_in[0];
    const float* tau   = (const float*)d_in[1];
    const float* Wqkv  = (const float*)d_in[2];
    const float* bqkv  = (const float*)d_in[3];
    const float* Wproj = (const float*)d_in[4];
    const float* bproj = (const float*)d_in[5];

    float* out_main = (float*)d_out;
    float* out_tau  = out_main + (size_t)NROW * CC;

    void *p_qkv, *p_ao, *p_ahi, *p_alo, *p_wthi, *p_wtlo, *p_wphi, *p_wplo, *p_aohi, *p_aolo;
    cudaGetSymbolAddress(&p_qkv, g_qkv);
    cudaGetSymbolAddress(&p_ao, g_attn_out);
    cudaGetSymbolAddress(&p_ahi, g_a_hi);  cudaGetSymbolAddress(&p_alo, g_a_lo);
    cudaGetSymbolAddress(&p_wthi, g_wt_hi); cudaGetSymbolAddress(&p_wtlo, g_wt_lo);
    cudaGetSymbolAddress(&p_wphi, g_wp_hi); cudaGetSymbolAddress(&p_wplo, g_wp_lo);
    cudaGetSymbolAddress(&p_aohi, g_ao_hi); cudaGetSymbolAddress(&p_aolo, g_ao_lo);

    cudaFuncSetAttribute(gemm3_kernel, cudaFuncAttributeMaxDynamicSharedMemorySize, GEMM_SMEM);

    // 1. top-4 + rowsum of tau per row
    topk_kernel<<<NROW, 256>>>(tau);

    // 2. operand prep: x split; W transposed+split
    convert_split<<<(NROW * KTOT) / 256, 256>>>(x, (__nv_bfloat16*)p_ahi, (__nv_bfloat16*)p_alo, NROW * KTOT);
    transpose_split<<<dim3(C3 / 32, KTOT / 32), dim3(32, 8)>>>(Wqkv, (__nv_bfloat16*)p_wthi, (__nv_bfloat16*)p_wtlo, KTOT, C3);
    transpose_split<<<dim3(CC / 32, KTOT / 32), dim3(32, 8)>>>(Wproj, (__nv_bfloat16*)p_wphi, (__nv_bfloat16*)p_wplo, KTOT, CC);

    // 3. QKV GEMM (HMMA, 3x bf16): [4096,512] x [512,1536]
    gemm3_kernel<<<dim3(C3 / 128, NROW / 128), 256, GEMM_SMEM>>>(
        (const __nv_bfloat16*)p_ahi, (const __nv_bfloat16*)p_alo,
        (const __nv_bfloat16*)p_wthi, (const __nv_bfloat16*)p_wtlo,
        bqkv, (float*)p_qkv, C3);

    // 4. sparse attention (4 keys/query) + signal + denominator
    attn_kernel<<<NROW, 256>>>(tau);

    // 5. tau_new streaming pass + fixup
    tau_scale<<<(NROW * TT / 4) / 256, 256>>>(tau, out_tau);
    tau_fix<<<(NROW * KSEL + 255) / 256, 256>>>(tau, out_tau);

    // 6. attn_out split, proj GEMM -> d_out
    convert_split<<<(NROW * KTOT) / 256, 256>>>((const float*)p_ao, (__nv_bfloat16*)p_aohi, (__nv_bfloat16*)p_aolo, NROW * KTOT);
    gemm3_kernel<<<dim3(CC / 128, NROW / 128), 256, GEMM_SMEM>>>(
        (const __nv_bfloat16*)p_aohi, (const __nv_bfloat16*)p_aolo,
        (const __nv_bfloat16*)p_wphi, (const __nv_bfloat16*)p_wplo,
        bproj, out_main, CC);
}